// round 1
// baseline (speedup 1.0000x reference)
#include <cuda_runtime.h>
#include <math.h>

#define NN 30000
#define EE 300000
#define DD 256
#define HH 8
#define CC 32
#define HID 256

// ---------------- scratch (device globals; no allocation allowed) -----------
__device__ float g_q[NN * HID];
__device__ float g_k[NN * HID];
__device__ float g_v[NN * HID];
__device__ float g_skip[NN * HID];
__device__ float g_e[EE * HID];          // 307 MB edge projection
__device__ float g_logits[EE * HH];
__device__ float g_m[NN * HH];
__device__ float g_denom[NN * HH];
__device__ float g_num[NN * HID];
__device__ float g_out[NN * HID];
__device__ float g_h1[NN * HID];

// ---------------- helpers ----------------------------------------------------
__device__ __forceinline__ float gelu_tanh(float x) {
    float x3 = x * x * x;
    float t = tanhf(0.7978845608028654f * (x + 0.044715f * x3));
    return 0.5f * x * (1.0f + t);
}

__device__ __forceinline__ void atomicMaxF(float* addr, float val) {
    if (val >= 0.0f)
        atomicMax(reinterpret_cast<int*>(addr), __float_as_int(val));
    else
        atomicMin(reinterpret_cast<unsigned int*>(addr), __float_as_uint(val));
}

// ---------------- SGEMM: C[M,256] = op(A[M,K] @ W[K,256] (+bias) (gelu) (+res))
// BM=64, BN=64, BK=16, 256 threads, 4x4 microtile per thread.
template <bool BIAS, bool GELU_F, bool RES>
__global__ void sgemm256(const float* __restrict__ A,
                         const float* __restrict__ W,
                         const float* __restrict__ bias,
                         const float* __restrict__ res,
                         float* __restrict__ C,
                         int M, int K) {
    const int BM = 64, BN = 64, BK = 16;
    __shared__ float As[BK][BM];
    __shared__ float Ws[BK][BN];

    int tid = threadIdx.x;
    int bm = blockIdx.x * BM;
    int bn = blockIdx.y * BN;
    int ty = tid / 16;          // 0..15 -> row group
    int tx = tid % 16;          // 0..15 -> col group

    // A-load mapping: 64 rows x 16 k, float4 per thread
    int lmm = tid >> 2;         // 0..63
    int lkk = (tid & 3) * 4;    // 0,4,8,12
    // W-load mapping: 16 k x 64 n, float4 per thread
    int wkk = tid >> 4;         // 0..15
    int wnn = (tid & 15) * 4;   // 0..60

    float acc[4][4];
#pragma unroll
    for (int i = 0; i < 4; i++)
#pragma unroll
        for (int j = 0; j < 4; j++) acc[i][j] = 0.0f;

    for (int k0 = 0; k0 < K; k0 += BK) {
        float4 av = make_float4(0.f, 0.f, 0.f, 0.f);
        int row = bm + lmm;
        if (row < M)
            av = *reinterpret_cast<const float4*>(A + (size_t)row * K + k0 + lkk);
        As[lkk + 0][lmm] = av.x;
        As[lkk + 1][lmm] = av.y;
        As[lkk + 2][lmm] = av.z;
        As[lkk + 3][lmm] = av.w;

        float4 wv = *reinterpret_cast<const float4*>(W + (size_t)(k0 + wkk) * 256 + bn + wnn);
        *reinterpret_cast<float4*>(&Ws[wkk][wnn]) = wv;
        __syncthreads();

#pragma unroll
        for (int kk = 0; kk < BK; kk++) {
            float a[4], b[4];
#pragma unroll
            for (int i = 0; i < 4; i++) a[i] = As[kk][ty * 4 + i];
#pragma unroll
            for (int j = 0; j < 4; j++) b[j] = Ws[kk][tx * 4 + j];
#pragma unroll
            for (int i = 0; i < 4; i++)
#pragma unroll
                for (int j = 0; j < 4; j++) acc[i][j] += a[i] * b[j];
        }
        __syncthreads();
    }

#pragma unroll
    for (int i = 0; i < 4; i++) {
        int row = bm + ty * 4 + i;
        if (row >= M) continue;
#pragma unroll
        for (int j = 0; j < 4; j++) {
            int col = bn + tx * 4 + j;
            float v = acc[i][j];
            if (BIAS) v += bias[col];
            if (GELU_F) v = gelu_tanh(v);
            if (RES) v += res[(size_t)row * 256 + col];
            C[(size_t)row * 256 + col] = v;
        }
    }
}

// ---------------- init: m=-inf, denom=0, num=0 -------------------------------
__global__ void init_kernel() {
    int i = blockIdx.x * blockDim.x + threadIdx.x;
    if (i < NN * HH) {
        g_m[i] = -INFINITY;
        g_denom[i] = 0.0f;
    }
    if (i < NN * HID) g_num[i] = 0.0f;
}

// ---------------- pass A: per-edge logits + segment max ----------------------
__global__ void edge_logits_kernel(const int* __restrict__ ei) {
    int warp = (blockIdx.x * blockDim.x + threadIdx.x) >> 5;
    int lane = threadIdx.x & 31;
    if (warp >= EE) return;
    int src = ei[warp];
    int dst = ei[EE + warp];
    const float* qrow = g_q + (size_t)dst * 256;
    const float* krow = g_k + (size_t)src * 256;
    const float* erow = g_e + (size_t)warp * 256;

    float s[8];
#pragma unroll
    for (int h = 0; h < 8; h++) {
        int j = h * 32 + lane;
        s[h] = qrow[j] * (krow[j] + erow[j]);
    }
#pragma unroll
    for (int off = 16; off; off >>= 1)
#pragma unroll
        for (int h = 0; h < 8; h++) s[h] += __shfl_xor_sync(0xffffffffu, s[h], off);

    if (lane < 8) {
        float lg = s[lane] * 0.17677669529663687f;  // 1/sqrt(32)
        g_logits[(size_t)warp * 8 + lane] = lg;
        atomicMaxF(&g_m[dst * 8 + lane], lg);
    }
}

// ---------------- pass B: exp, denom, numerator accumulation -----------------
__global__ void edge_accum_kernel(const int* __restrict__ ei) {
    int warp = (blockIdx.x * blockDim.x + threadIdx.x) >> 5;
    int lane = threadIdx.x & 31;
    if (warp >= EE) return;
    int src = ei[warp];
    int dst = ei[EE + warp];

    float a = 0.0f;
    if (lane < 8) {
        a = expf(g_logits[(size_t)warp * 8 + lane] - g_m[dst * 8 + lane]);
        atomicAdd(&g_denom[dst * 8 + lane], a);
    }
    float ah[8];
#pragma unroll
    for (int h = 0; h < 8; h++) ah[h] = __shfl_sync(0xffffffffu, a, h);

    const float* vrow = g_v + (size_t)src * 256;
    const float* erow = g_e + (size_t)warp * 256;
    float* nrow = g_num + (size_t)dst * 256;
#pragma unroll
    for (int h = 0; h < 8; h++) {
        int j = h * 32 + lane;
        atomicAdd(&nrow[j], ah[h] * (vrow[j] + erow[j]));
    }
}

// ---------------- node epilogue: out = num/denom + skip ----------------------
__global__ void node_out_kernel() {
    int i = blockIdx.x * blockDim.x + threadIdx.x;
    if (i >= NN * HID) return;
    int n = i >> 8;
    int h = (i & 255) >> 5;
    g_out[i] = g_num[i] / (g_denom[n * 8 + h] + 1e-16f) + g_skip[i];
}

// ---------------- launch ------------------------------------------------------
extern "C" void kernel_launch(void* const* d_in, const int* in_sizes, int n_in,
                              void* d_out, int out_size) {
    const float* x         = (const float*)d_in[0];
    const int*   edge_idx  = (const int*)d_in[1];
    const float* edge_attr = (const float*)d_in[2];
    const float* Wq = (const float*)d_in[3];
    const float* bq = (const float*)d_in[4];
    const float* Wk = (const float*)d_in[5];
    const float* bk = (const float*)d_in[6];
    const float* Wv = (const float*)d_in[7];
    const float* bv = (const float*)d_in[8];
    const float* We = (const float*)d_in[9];
    const float* Wskip = (const float*)d_in[10];
    const float* W1 = (const float*)d_in[11];
    const float* b1 = (const float*)d_in[12];
    const float* W2 = (const float*)d_in[13];
    const float* b2 = (const float*)d_in[14];

    void *pq, *pk, *pv, *pskip, *pe, *pnum_unused, *pout, *ph1;
    cudaGetSymbolAddress(&pq, g_q);
    cudaGetSymbolAddress(&pk, g_k);
    cudaGetSymbolAddress(&pv, g_v);
    cudaGetSymbolAddress(&pskip, g_skip);
    cudaGetSymbolAddress(&pe, g_e);
    cudaGetSymbolAddress(&pout, g_out);
    cudaGetSymbolAddress(&ph1, g_h1);
    (void)pnum_unused;

    dim3 blk(256);
    dim3 gN((NN + 63) / 64, 4);
    dim3 gE((EE + 63) / 64, 4);

    // init accumulators
    init_kernel<<<(NN * HID + 255) / 256, 256>>>();

    // Q, K, V (bias), skip (no bias)
    sgemm256<true,  false, false><<<gN, blk>>>(x, Wq, bq, nullptr, (float*)pq, NN, 256);
    sgemm256<true,  false, false><<<gN, blk>>>(x, Wk, bk, nullptr, (float*)pk, NN, 256);
    sgemm256<true,  false, false><<<gN, blk>>>(x, Wv, bv, nullptr, (float*)pv, NN, 256);
    sgemm256<false, false, false><<<gN, blk>>>(x, Wskip, nullptr, nullptr, (float*)pskip, NN, 256);

    // edge projection: e = edge_attr @ We
    sgemm256<false, false, false><<<gE, blk>>>(edge_attr, We, nullptr, nullptr, (float*)pe, EE, 32);

    // attention passes (warp per edge)
    int edgeBlocks = (EE * 32 + 255) / 256;
    edge_logits_kernel<<<edgeBlocks, 256>>>(edge_idx);
    edge_accum_kernel<<<edgeBlocks, 256>>>(edge_idx);

    // out = num/denom + skip
    node_out_kernel<<<(NN * HID + 255) / 256, 256>>>();

    // MLP: h1 = gelu(out@W1+b1); final = out + gelu(h1@W2+b2)
    sgemm256<true, true, false><<<gN, blk>>>((const float*)pout, W1, b1, nullptr, (float*)ph1, NN, 256);
    sgemm256<true, true, true><<<gN, blk>>>((const float*)ph1, W2, b2, (const float*)pout,
                                            (float*)d_out, NN, 256);
}